// round 6
// baseline (speedup 1.0000x reference)
#include <cuda_runtime.h>

#define EPS_F 1e-8f
#define TOL_F 1e-6f
#define LOSS_EPS_F 1e-6f

__global__ void hx_zero_out(float* out) { out[0] = 0.0f; }

__global__ __launch_bounds__(256)
void diou3d_loss_kernel(const float* __restrict__ pred,
                        const float* __restrict__ tgt,
                        float* __restrict__ out, int n)
{
    int i = blockIdx.x * blockDim.x + threadIdx.x;
    float loss = 0.0f;
    if (i < n) {
        float p[7], t[7];
#pragma unroll
        for (int k = 0; k < 7; k++) { p[k] = pred[i * 7 + k]; t[k] = tgt[i * 7 + k]; }

        float cp, sp, ct, st;
        __sincosf(p[6], &sp, &cp);
        __sincosf(t[6], &st, &ct);

        // ---- 2D corners ----
        float c1x[4], c1y[4], c2x[4], c2y[4];
        {
            const float sx[4] = {0.5f, -0.5f, -0.5f, 0.5f};
            const float sy[4] = {0.5f, 0.5f, -0.5f, -0.5f};
#pragma unroll
            for (int k = 0; k < 4; k++) {
                float x4 = sx[k] * p[3], y4 = sy[k] * p[4];
                c1x[k] = x4 * cp - y4 * sp + p[0];
                c1y[k] = x4 * sp + y4 * cp + p[1];
                float xt = sx[k] * t[3], yt = sy[k] * t[4];
                c2x[k] = xt * ct - yt * st + t[0];
                c2y[k] = xt * st + yt * ct + t[1];
            }
        }

        // ---- branchless candidate collection ----
        float vx[24], vy[24];
        int cnt = 0;
        float sumx = 0.0f, sumy = 0.0f;

        // corners of box1 inside box2
        {
            float ax = c2x[0], ay = c2y[0];
            float abx = c2x[1] - ax, aby = c2y[1] - ay;
            float adx = c2x[3] - ax, ady = c2y[3] - ay;
            float iab = __fdividef(1.0f, abx * abx + aby * aby);
            float iad = __fdividef(1.0f, adx * adx + ady * ady);
#pragma unroll
            for (int k = 0; k < 4; k++) {
                float amx = c1x[k] - ax, amy = c1y[k] - ay;
                float pab = (abx * amx + aby * amy) * iab;
                float pad = (adx * amx + ady * amy) * iad;
                bool in = (pab > -TOL_F) & (pab < 1.0f + TOL_F) & (pad > -TOL_F) & (pad < 1.0f + TOL_F);
                vx[cnt] = c1x[k]; vy[cnt] = c1y[k];
                sumx += in ? c1x[k] : 0.0f; sumy += in ? c1y[k] : 0.0f;
                cnt += in;
            }
        }
        // corners of box2 inside box1
        {
            float ax = c1x[0], ay = c1y[0];
            float abx = c1x[1] - ax, aby = c1y[1] - ay;
            float adx = c1x[3] - ax, ady = c1y[3] - ay;
            float iab = __fdividef(1.0f, abx * abx + aby * aby);
            float iad = __fdividef(1.0f, adx * adx + ady * ady);
#pragma unroll
            for (int k = 0; k < 4; k++) {
                float amx = c2x[k] - ax, amy = c2y[k] - ay;
                float pab = (abx * amx + aby * amy) * iab;
                float pad = (adx * amx + ady * amy) * iad;
                bool in = (pab > -TOL_F) & (pab < 1.0f + TOL_F) & (pad > -TOL_F) & (pad < 1.0f + TOL_F);
                vx[cnt] = c2x[k]; vy[cnt] = c2y[k];
                sumx += in ? c2x[k] : 0.0f; sumy += in ? c2y[k] : 0.0f;
                cnt += in;
            }
        }
        // edge-edge intersections (16 pairs, branchless)
#pragma unroll
        for (int a = 0; a < 4; a++) {
            float x1 = c1x[a], y1 = c1y[a];
            float ex1 = c1x[(a + 1) & 3] - x1, ey1 = c1y[(a + 1) & 3] - y1;
#pragma unroll
            for (int b = 0; b < 4; b++) {
                float x3 = c2x[b], y3 = c2y[b];
                float ex2 = c2x[(b + 1) & 3] - x3, ey2 = c2y[(b + 1) & 3] - y3;
                float num  = ey2 * ex1 - ex2 * ey1;
                float dx13 = x1 - x3, dy13 = y1 - y3;
                float dent = ex2 * dy13 - ey2 * dx13;
                float denu = ex1 * dy13 - ey1 * dx13;
                float rn = __fdividef(1.0f, num);            // num==0 -> inf, compares false below
                float tt = dent * rn;
                float uu = -denu * rn;
                bool m = (num != 0.0f) & (tt > 0.0f) & (tt < 1.0f) & (uu > 0.0f) & (uu < 1.0f);
                float t2 = __fdividef(dent, num + EPS_F);
                float px = x1 + t2 * ex1;
                float py = y1 + t2 * ey1;
                vx[cnt] = px; vy[cnt] = py;
                sumx += m ? px : 0.0f; sumy += m ? py : 0.0f;
                cnt += m;
            }
        }

        // ---- angle keys around centroid (no write-back of centered coords) ----
        unsigned key[24], skey[24];
        {
            float inv = __fdividef(1.0f, (float)(cnt > 0 ? cnt : 1));
            float mx = sumx * inv, my = sumy * inv;
            for (int k = 0; k < cnt; k++) {
                float x = vx[k] - mx, y = vy[k] - my;
                // pseudo-angle in [0,4): same cyclic order as atan2
                float tt = __fdividef(x, fabsf(x) + fabsf(y) + 1e-30f);
                float a = (y >= 0.0f) ? (1.0f - tt) : (3.0f + tt);
                key[k] = (__float_as_uint(a) & 0xFFFFFFE0u) | (unsigned)k;
            }
        }

        // ---- branchless rank sort (keys unique via low-bit index) ----
        for (int k = 0; k < cnt; k++) {
            unsigned a = key[k];
            int r = 0;
            for (int j = 0; j < cnt; j++) r += (key[j] < a);
            skey[r] = a;
        }

        // ---- shoelace, anchored at first sorted vertex (translation-invariant) ----
        float area = 0.0f;
        if (cnt >= 3) {
            unsigned id0 = skey[0] & 31u;
            float ox = vx[id0], oy = vy[id0];
            float lx = 0.0f, ly = 0.0f, s = 0.0f;
            for (int k = 1; k < cnt; k++) {
                unsigned id = skey[k] & 31u;
                float x = vx[id] - ox, y = vy[id] - oy;
                s += lx * y - ly * x;
                lx = x; ly = y;
            }
            area = 0.5f * fabsf(s);
        }

        // ---- 3D IoU ----
        float zov = fmaxf(fminf(p[2] + 0.5f * p[5], t[2] + 0.5f * t[5]) -
                          fmaxf(p[2] - 0.5f * p[5], t[2] - 0.5f * t[5]), 0.0f);
        float inter3 = area * zov;
        float vol1 = p[3] * p[4] * p[5];
        float vol2 = t[3] * t[4] * t[5];
        float iou = inter3 / (vol1 + vol2 - inter3);
        if (isnan(iou)) iou = 0.0f;

        // ---- center distance ----
        float d0 = p[0] - t[0], d1 = p[1] - t[1], d2 = p[2] - t[2];
        float ctd = d0 * d0 + d1 * d1 + d2 * d2;

        // ---- corner distance, closed form (verified in R5) ----
        float alpha = p[3] * cp - t[3] * ct;
        float gamma = p[3] * sp - t[3] * st;
        float beta  = p[5] * sp - t[5] * st;
        float delta = p[5] * cp - t[5] * ct;
        float epsi  = p[4] - t[4];
        float cnd = ctd + 0.25f * (alpha * alpha + beta * beta + gamma * gamma +
                                   delta * delta + epsi * epsi);

        float did = t[3] * t[3] + t[4] * t[4] + t[5] * t[5];
        float sreg = ctd + cnd;
        float reg = __fdividef(sreg, sreg + did + LOSS_EPS_F);
        loss = 1.0f - iou + reg;
    }

    // ---- block reduction + atomic ----
#pragma unroll
    for (int off = 16; off; off >>= 1)
        loss += __shfl_down_sync(0xffffffff, loss, off);

    __shared__ float warpsum[8];
    int lane = threadIdx.x & 31, wid = threadIdx.x >> 5;
    if (lane == 0) warpsum[wid] = loss;
    __syncthreads();
    if (wid == 0) {
        float s = (lane < 8) ? warpsum[lane] : 0.0f;
#pragma unroll
        for (int off = 4; off; off >>= 1)
            s += __shfl_down_sync(0xffffffff, s, off);
        if (lane == 0) atomicAdd(out, s * (1.0f / (float)n));
    }
}

extern "C" void kernel_launch(void* const* d_in, const int* in_sizes, int n_in,
                              void* d_out, int out_size)
{
    const float* pred = (const float*)d_in[0];
    const float* tgt  = (const float*)d_in[1];
    float* out = (float*)d_out;
    int n = in_sizes[0] / 7;

    hx_zero_out<<<1, 1>>>(out);
    diou3d_loss_kernel<<<(n + 255) / 256, 256>>>(pred, tgt, out, n);
}

// round 8
// speedup vs baseline: 1.9730x; 1.9730x over previous
#include <cuda_runtime.h>

#define TOL_F 1e-6f
#define LOSS_EPS_F 1e-6f

__global__ void hx_zero_out(float* out) { out[0] = 0.0f; }

__global__ __launch_bounds__(256)
void diou3d_loss_kernel(const float* __restrict__ pred,
                        const float* __restrict__ tgt,
                        float* __restrict__ out, int n)
{
    int i = blockIdx.x * blockDim.x + threadIdx.x;
    float loss = 0.0f;
    if (i < n) {
        float p[7], t[7];
#pragma unroll
        for (int k = 0; k < 7; k++) { p[k] = pred[i * 7 + k]; t[k] = tgt[i * 7 + k]; }

        float cp, sp, ct, st;
        __sincosf(p[6], &sp, &cp);
        __sincosf(t[6], &st, &ct);

        // ---- box2's axis-aligned frame ----
        float W = 0.5f * t[3], H = 0.5f * t[4];          // box2 half-dims
        float w1h = 0.5f * p[3], h1h = 0.5f * p[4];      // box1 half-dims
        float cd = cp * ct + sp * st;                     // cos(a1-a2)
        float sd = sp * ct - cp * st;                     // sin(a1-a2)
        float dx0 = p[0] - t[0], dy0 = p[1] - t[1];
        float qx =  ct * dx0 + st * dy0;                  // box1 center in frame2
        float qy = -st * dx0 + ct * dy0;

        // box1 corners in frame2 (same order as reference: (+,+)(-,+)(-,-)(+,-))
        float c1x[4], c1y[4];
        {
            const float sx[4] = {1.0f, -1.0f, -1.0f, 1.0f};
            const float sy[4] = {1.0f, 1.0f, -1.0f, -1.0f};
#pragma unroll
            for (int k = 0; k < 4; k++) {
                float ox = sx[k] * w1h, oy = sy[k] * h1h;
                c1x[k] = qx + ox * cd - oy * sd;
                c1y[k] = qy + ox * sd + oy * cd;
            }
        }

        float vx[24], vy[24];
        int cnt = 0;
        float sumx = 0.0f, sumy = 0.0f;

        // corners of box1 inside box2 (reference box_in_box, normalized tol)
        {
            float bx = fmaf(TOL_F, t[3], W);
            float by = fmaf(TOL_F, t[4], H);
#pragma unroll
            for (int k = 0; k < 4; k++) {
                if (fabsf(c1x[k]) < bx && fabsf(c1y[k]) < by) {
                    vx[cnt] = c1x[k]; vy[cnt] = c1y[k];
                    sumx += c1x[k]; sumy += c1y[k]; cnt++;
                }
            }
        }
        // corners of box2 inside box1
        {
            float bx = fmaf(TOL_F, p[3], w1h);
            float by = fmaf(TOL_F, p[4], h1h);
            const float kxs[4] = {1.0f, -1.0f, -1.0f, 1.0f};
            const float kys[4] = {1.0f, 1.0f, -1.0f, -1.0f};
#pragma unroll
            for (int k = 0; k < 4; k++) {
                float kx = kxs[k] * W, ky = kys[k] * H;
                float rx = kx - qx, ry = ky - qy;
                float mx = cd * rx + sd * ry;
                float my = -sd * rx + cd * ry;
                if (fabsf(mx) < bx && fabsf(my) < by) {
                    vx[cnt] = kx; vy[cnt] = ky;
                    sumx += kx; sumy += ky; cnt++;
                }
            }
        }

        // box1 edges vs box2 edge LINES, replicating the reference's sign-flipped u:
        // accept iff t in (0,1) and u_ref = -u_true in (0,1)  (phantom windows).
        // Windows (from reference corner order K0..K3):
        //   line x=+W : yv in (-3H, -H)     line x=-W : yv in (H, 3H)
        //   line y=+H : xv in (W, 3W)       line y=-H : xv in (-3W, -W)
        float W3 = 3.0f * W, H3 = 3.0f * H;
#pragma unroll
        for (int a = 0; a < 4; a++) {
            float x1 = c1x[a], y1 = c1y[a];
            float dxe = c1x[(a + 1) & 3] - x1, dye = c1y[(a + 1) & 3] - y1;
            float rdx = __fdividef(1.0f, dxe);   // dxe==0 -> inf/NaN -> tests fail (num==0)
            float rdy = __fdividef(1.0f, dye);

            float tt = (W - x1) * rdx;           // line x=+W
            if (tt > 0.0f && tt < 1.0f) {
                float yv = fmaf(tt, dye, y1);
                if (yv > -H3 && yv < -H) {
                    vx[cnt] = W; vy[cnt] = yv;
                    sumx += W; sumy += yv; cnt++;
                }
            }
            tt = (-W - x1) * rdx;                // line x=-W
            if (tt > 0.0f && tt < 1.0f) {
                float yv = fmaf(tt, dye, y1);
                if (yv > H && yv < H3) {
                    vx[cnt] = -W; vy[cnt] = yv;
                    sumx += -W; sumy += yv; cnt++;
                }
            }
            tt = (H - y1) * rdy;                 // line y=+H
            if (tt > 0.0f && tt < 1.0f) {
                float xv = fmaf(tt, dxe, x1);
                if (xv > W && xv < W3) {
                    vx[cnt] = xv; vy[cnt] = H;
                    sumx += xv; sumy += H; cnt++;
                }
            }
            tt = (-H - y1) * rdy;                // line y=-H
            if (tt > 0.0f && tt < 1.0f) {
                float xv = fmaf(tt, dxe, x1);
                if (xv > -W3 && xv < -W) {
                    vx[cnt] = xv; vy[cnt] = -H;
                    sumx += xv; sumy += -H; cnt++;
                }
            }
        }

        // ---- pseudo-angle keys around mean + insertion sort + shoelace (R2-proven) ----
        float area = 0.0f;
        if (cnt > 0) {
            unsigned key[24];
            float inv = __fdividef(1.0f, (float)cnt);
            float mx = sumx * inv, my = sumy * inv;
            for (int k = 0; k < cnt; k++) {
                float x = vx[k] - mx, y = vy[k] - my;
                float tt = __fdividef(x, fabsf(x) + fabsf(y) + 1e-30f);
                float a = (y >= 0.0f) ? (1.0f - tt) : (3.0f + tt);
                key[k] = (__float_as_uint(a) & 0xFFFFFFE0u) | (unsigned)k;
            }
            for (int k = 1; k < cnt; k++) {
                unsigned a = key[k];
                int j = k - 1;
                while (j >= 0 && key[j] > a) { key[j + 1] = key[j]; j--; }
                key[j + 1] = a;
            }
            unsigned k0 = key[0] & 31u;
            float fx = vx[k0] - mx, fy = vy[k0] - my;
            float px = fx, py = fy, s = 0.0f;
            for (int k = 1; k < cnt; k++) {
                unsigned id = key[k] & 31u;
                float x = vx[id] - mx, y = vy[id] - my;
                s += px * y - py * x;
                px = x; py = y;
            }
            s += px * fy - py * fx;
            area = 0.5f * fabsf(s);
        }

        // ---- 3D IoU ----
        float zov = fmaxf(fminf(p[2] + 0.5f * p[5], t[2] + 0.5f * t[5]) -
                          fmaxf(p[2] - 0.5f * p[5], t[2] - 0.5f * t[5]), 0.0f);
        float inter3 = area * zov;
        float vol1 = p[3] * p[4] * p[5];
        float vol2 = t[3] * t[4] * t[5];
        float iou = inter3 / (vol1 + vol2 - inter3);
        if (isnan(iou)) iou = 0.0f;

        // ---- center distance ----
        float ctd = dx0 * dx0 + dy0 * dy0 + (p[2] - t[2]) * (p[2] - t[2]);

        // ---- corner distance, closed form (verified in R5) ----
        float alpha = p[3] * cp - t[3] * ct;
        float gamma = p[3] * sp - t[3] * st;
        float beta  = p[5] * sp - t[5] * st;
        float delta = p[5] * cp - t[5] * ct;
        float epsi  = p[4] - t[4];
        float cnd = ctd + 0.25f * (alpha * alpha + beta * beta + gamma * gamma +
                                   delta * delta + epsi * epsi);

        float did = t[3] * t[3] + t[4] * t[4] + t[5] * t[5];
        float sreg = ctd + cnd;
        float reg = __fdividef(sreg, sreg + did + LOSS_EPS_F);
        loss = 1.0f - iou + reg;
    }

    // ---- block reduction + atomic ----
#pragma unroll
    for (int off = 16; off; off >>= 1)
        loss += __shfl_down_sync(0xffffffff, loss, off);

    __shared__ float warpsum[8];
    int lane = threadIdx.x & 31, wid = threadIdx.x >> 5;
    if (lane == 0) warpsum[wid] = loss;
    __syncthreads();
    if (wid == 0) {
        float s = (lane < 8) ? warpsum[lane] : 0.0f;
#pragma unroll
        for (int off = 4; off; off >>= 1)
            s += __shfl_down_sync(0xffffffff, s, off);
        if (lane == 0) atomicAdd(out, s * (1.0f / (float)n));
    }
}

extern "C" void kernel_launch(void* const* d_in, const int* in_sizes, int n_in,
                              void* d_out, int out_size)
{
    const float* pred = (const float*)d_in[0];
    const float* tgt  = (const float*)d_in[1];
    float* out = (float*)d_out;
    int n = in_sizes[0] / 7;

    hx_zero_out<<<1, 1>>>(out);
    diou3d_loss_kernel<<<(n + 255) / 256, 256>>>(pred, tgt, out, n);
}